// round 1
// baseline (speedup 1.0000x reference)
#include <cuda_runtime.h>

// Spatial correlation sampler: out[b][dy][dx][y][x] =
//   sum_c in1[b,c,y,x] * in2[b,c,y+dy-4,x+dx-4]   (zero padded), dy,dx in 0..8
//
// Strategy:
//  - 1 thread = 4 consecutive x pixels, one y row, one dy-group (3 of 9 dys).
//  - 27 (dy,dx) accumulators per thread kept as f32x2 pairs (fma.rn.f32x2).
//  - Window operands loaded directly with LDG.128; overlap between adjacent
//    lanes is served by L1. Left/right edge vectors are exactly the OOB part
//    for lane 0 / lane 31 -> zeroed by predicate.
//  - dy-group is the fastest block index so the 3 passes over each row tile
//    are adjacent -> input re-reads hit L2, HBM reads inputs ~once.

#define CC 128
#define HH 96
#define WW 128
#define HW (HH * WW)

typedef unsigned long long ull;

__device__ __forceinline__ ull pk(float lo, float hi) {
    ull r;
    asm("mov.b64 %0, {%1,%2};"
        : "=l"(r)
        : "r"(__float_as_uint(lo)), "r"(__float_as_uint(hi)));
    return r;
}

__device__ __forceinline__ void fma2(ull& acc, ull a, ull b) {
    asm("fma.rn.f32x2 %0, %1, %2, %0;" : "+l"(acc) : "l"(a), "l"(b));
}

__device__ __forceinline__ float2 unpk(ull v) {
    unsigned lo, hi;
    asm("mov.b64 {%0,%1}, %2;" : "=r"(lo), "=r"(hi) : "l"(v));
    return make_float2(__uint_as_float(lo), __uint_as_float(hi));
}

__global__ __launch_bounds__(128) void corr_kernel(
    const float* __restrict__ in1,
    const float* __restrict__ in2,
    float* __restrict__ out)
{
    const int lane = threadIdx.x & 31;
    const int warp = threadIdx.x >> 5;

    const int bx      = blockIdx.x;
    const int group   = bx % 3;      // dy in {3*group, 3*group+1, 3*group+2}
    const int rowtile = bx / 3;      // 0..23
    const int y  = rowtile * 4 + warp;   // 0..95 (4 warps per block)
    const int b  = blockIdx.y;
    const int x0 = lane * 4;

    // 27 shift accumulators, each as two f32x2 pairs (pixels x0..x0+3)
    ull acc[3][9][2];
    #pragma unroll
    for (int g = 0; g < 3; g++)
        #pragma unroll
        for (int d = 0; d < 9; d++) {
            acc[g][d][0] = 0ull;
            acc[g][d][1] = 0ull;
        }

    const float* p1     = in1 + ((size_t)b * CC) * HW + (size_t)y * WW + x0;
    const float* p2base = in2 + ((size_t)b * CC) * HW;

    int  ys[3];
    bool ok[3];
    #pragma unroll
    for (int g = 0; g < 3; g++) {
        int yy = y + 3 * group + g - 4;
        ys[g] = yy;
        ok[g] = (yy >= 0) && (yy < HH);
    }

    #pragma unroll 2
    for (int c = 0; c < CC; c++) {
        const float4 av = *(const float4*)(p1 + (size_t)c * HW);
        const ull a01 = pk(av.x, av.y);
        const ull a23 = pk(av.z, av.w);

        #pragma unroll
        for (int g = 0; g < 3; g++) {
            if (!ok[g]) continue;   // warp-uniform predicate
            const float* pr = p2base + (size_t)c * HW + (size_t)ys[g] * WW + x0;

            float4 Lv = make_float4(0.f, 0.f, 0.f, 0.f);
            float4 Rv = make_float4(0.f, 0.f, 0.f, 0.f);
            if (lane != 0)  Lv = *(const float4*)(pr - 4);
            const float4 Mv = *(const float4*)(pr);
            if (lane != 31) Rv = *(const float4*)(pr + 4);

            // window w[k] = in2[.., x0 - 4 + k], k = 0..11
            const float w[12] = {Lv.x, Lv.y, Lv.z, Lv.w,
                                 Mv.x, Mv.y, Mv.z, Mv.w,
                                 Rv.x, Rv.y, Rv.z, Rv.w};

            // pre-pack the 11 overlapping pairs (w[k], w[k+1])
            ull wp[11];
            #pragma unroll
            for (int k = 0; k < 11; k++) wp[k] = pk(w[k], w[k + 1]);

            #pragma unroll
            for (int d = 0; d < 9; d++) {
                // pixels (x0, x0+1): B[x0+d-4], B[x0+d-3]  -> wp[d]
                fma2(acc[g][d][0], a01, wp[d]);
                // pixels (x0+2, x0+3):                      -> wp[d+2]
                fma2(acc[g][d][1], a23, wp[d + 2]);
            }
        }
    }

    // out[b][dy][dx][y][x], contiguous in x -> float4 stores
    #pragma unroll
    for (int g = 0; g < 3; g++) {
        const int dy = 3 * group + g;
        #pragma unroll
        for (int d = 0; d < 9; d++) {
            const float2 lo = unpk(acc[g][d][0]);
            const float2 hi = unpk(acc[g][d][1]);
            float* po = out + (((((size_t)b * 9 + dy) * 9 + d) * HH + y) * WW) + x0;
            *(float4*)po = make_float4(lo.x, lo.y, hi.x, hi.y);
        }
    }
}

extern "C" void kernel_launch(void* const* d_in, const int* in_sizes, int n_in,
                              void* d_out, int out_size)
{
    const float* in1 = (const float*)d_in[0];
    const float* in2 = (const float*)d_in[1];
    float* out = (float*)d_out;

    // bx = group + 3*rowtile ; 24 row tiles (96 rows / 4 warps) ; 8 batches
    dim3 grid(72, 8, 1);
    corr_kernel<<<grid, 128>>>(in1, in2, out);
}

// round 2
// speedup vs baseline: 1.3075x; 1.3075x over previous
#include <cuda_runtime.h>

// Spatial correlation sampler: out[b][dy][dx][y][x] =
//   sum_c in1[b,c,y,x] * in2[b,c,y+dy-4,x+dx-4]   (zero padded), dy,dx in 0..8
//
// Round-2 structure:
//  - 1 thread = 4 consecutive x pixels, one y row, one dy-group (3 of 9 dys).
//  - 27 (dy,dx) accumulators per thread as f32x2 pairs (fma.rn.f32x2).
//  - The channel loop is BRANCH-FREE: boundary handling is done by clamping
//    load addresses (always in-bounds) and letting garbage accumulate; every
//    garbage-touched output scalar is an exact-zero output, zeroed by a
//    precomputed mask at the epilogue.

#define CC 128
#define HH 96
#define WW 128
#define HW (HH * WW)

typedef unsigned long long ull;

__device__ __forceinline__ ull pk(float lo, float hi) {
    ull r;
    asm("mov.b64 %0, {%1,%2};"
        : "=l"(r)
        : "r"(__float_as_uint(lo)), "r"(__float_as_uint(hi)));
    return r;
}

__device__ __forceinline__ void fma2(ull& acc, ull a, ull b) {
    asm("fma.rn.f32x2 %0, %1, %2, %0;" : "+l"(acc) : "l"(a), "l"(b));
}

__device__ __forceinline__ float2 unpk(ull v) {
    unsigned lo, hi;
    asm("mov.b64 {%0,%1}, %2;" : "=r"(lo), "=r"(hi) : "l"(v));
    return make_float2(__uint_as_float(lo), __uint_as_float(hi));
}

__global__ __launch_bounds__(128) void corr_kernel(
    const float* __restrict__ in1,
    const float* __restrict__ in2,
    float* __restrict__ out)
{
    const int lane = threadIdx.x & 31;
    const int warp = threadIdx.x >> 5;

    const int bx      = blockIdx.x;
    const int group   = bx % 3;      // dy in {3*group, 3*group+1, 3*group+2}
    const int rowtile = bx / 3;      // 0..23
    const int y  = rowtile * 4 + warp;   // 0..95
    const int b  = blockIdx.y;
    const int x0 = lane * 4;

    // Clamped row indices + row-validity masks (applied at epilogue only).
    int   ysr[3];
    float rowok[3];
    #pragma unroll
    for (int g = 0; g < 3; g++) {
        int yy = y + 3 * group + g - 4;
        rowok[g] = (yy >= 0 && yy < HH) ? 1.0f : 0.0f;
        ysr[g] = yy < 0 ? 0 : (yy >= HH ? HH - 1 : yy);
    }

    // Clamped lane-edge offsets: lane 0 re-reads the M vector instead of
    // reading below the row; lane 31 likewise above. Garbage masked later.
    const int offL = (lane == 0)  ? 0 : -4;
    const int offR = (lane == 31) ? 0 :  4;

    ull acc[3][9][2];
    #pragma unroll
    for (int g = 0; g < 3; g++)
        #pragma unroll
        for (int d = 0; d < 9; d++) {
            acc[g][d][0] = 0ull;
            acc[g][d][1] = 0ull;
        }

    const float* p1 = in1 + ((size_t)b * CC) * HW + (size_t)y * WW + x0;
    const float* p2r[3];
    #pragma unroll
    for (int g = 0; g < 3; g++)
        p2r[g] = in2 + ((size_t)b * CC) * HW + (size_t)ysr[g] * WW + x0;

    // -------- branch-free hot loop --------
    #pragma unroll 2
    for (int c = 0; c < CC; c++) {
        const float4 av = *(const float4*)p1;
        p1 += HW;
        const ull a01 = pk(av.x, av.y);
        const ull a23 = pk(av.z, av.w);

        #pragma unroll
        for (int g = 0; g < 3; g++) {
            const float* pr = p2r[g];
            p2r[g] += HW;

            const float4 Lv = *(const float4*)(pr + offL);
            const float4 Mv = *(const float4*)(pr);
            const float4 Rv = *(const float4*)(pr + offR);

            const float w[12] = {Lv.x, Lv.y, Lv.z, Lv.w,
                                 Mv.x, Mv.y, Mv.z, Mv.w,
                                 Rv.x, Rv.y, Rv.z, Rv.w};

            ull wp[11];
            #pragma unroll
            for (int k = 0; k < 11; k++) wp[k] = pk(w[k], w[k + 1]);

            #pragma unroll
            for (int d = 0; d < 9; d++) {
                fma2(acc[g][d][0], a01, wp[d]);      // pixels x0, x0+1
                fma2(acc[g][d][1], a23, wp[d + 2]);  // pixels x0+2, x0+3
            }
        }
    }

    // -------- epilogue: zero every garbage-touched output scalar --------
    #pragma unroll
    for (int g = 0; g < 3; g++) {
        const int dy = 3 * group + g;
        #pragma unroll
        for (int d = 0; d < 9; d++) {
            const float2 lo = unpk(acc[g][d][0]);
            const float2 hi = unpk(acc[g][d][1]);
            float m[4];
            #pragma unroll
            for (int px = 0; px < 4; px++) {
                const int xs = x0 + px + d - 4;   // shifted source column
                m[px] = (xs >= 0 && xs < WW) ? rowok[g] : 0.0f;
            }
            float* po = out + (((((size_t)b * 9 + dy) * 9 + d) * HH + y) * WW) + x0;
            *(float4*)po = make_float4(lo.x * m[0], lo.y * m[1],
                                       hi.x * m[2], hi.y * m[3]);
        }
    }
}

extern "C" void kernel_launch(void* const* d_in, const int* in_sizes, int n_in,
                              void* d_out, int out_size)
{
    const float* in1 = (const float*)d_in[0];
    const float* in2 = (const float*)d_in[1];
    float* out = (float*)d_out;

    dim3 grid(72, 8, 1);   // bx = group + 3*rowtile, 24 row tiles; by = batch
    corr_kernel<<<grid, 128>>>(in1, in2, out);
}

// round 3
// speedup vs baseline: 1.3566x; 1.0375x over previous
#include <cuda_runtime.h>

// Spatial correlation sampler: out[b][dy][dx][y][x] =
//   sum_c in1[b,c,y,x] * in2[b,c,y+dy-4,x+dx-4]   (zero padded), dy,dx in 0..8
//
// Round-3 decomposition (anti-diagonal sharing):
//   Outputs with the same r = y + dy - 4 read the SAME in2 row r.
//   A thread owns: one in2 row r, one dy-group g (dy = 3g..3g+2), 4 x-pixels,
//   all 9 dx. Its 3 output rows are y_t = r + 4 - (3g+t).
//   Per channel: 3 LDG.128 (in2 window, shared by all 3 dy!) + 3 LDG.128 (in1)
//   feed 54 FFMA2 -> ~70% FMA issue density.
//   Window pairs loaded as ulonglong2 so even-offset f32x2 pairs are free;
//   only 5 odd-offset pairs are repacked.
//   Boundary handling: clamp all load addresses, mask at epilogue (exact zeros).

#define CC 128
#define HH 96
#define WW 128
#define HW (HH * WW)

typedef unsigned long long ull;

__device__ __forceinline__ void fma2(ull& acc, ull a, ull b) {
    asm("fma.rn.f32x2 %0, %1, %2, %0;" : "+l"(acc) : "l"(a), "l"(b));
}

// (hi of a, lo of b) -> pair (lo = a.hi, hi = b.lo)
__device__ __forceinline__ ull pkmid(ull a, ull b) {
    ull r;
    asm("{ .reg .b32 al, ah, bl, bh;\n\t"
        "  mov.b64 {al, ah}, %1;\n\t"
        "  mov.b64 {bl, bh}, %2;\n\t"
        "  mov.b64 %0, {ah, bl}; }"
        : "=l"(r) : "l"(a), "l"(b));
    return r;
}

__device__ __forceinline__ float2 unpk(ull v) {
    unsigned lo, hi;
    asm("mov.b64 {%0,%1}, %2;" : "=r"(lo), "=r"(hi) : "l"(v));
    return make_float2(__uint_as_float(lo), __uint_as_float(hi));
}

__global__ __launch_bounds__(288) void corr_kernel(
    const float* __restrict__ in1,
    const float* __restrict__ in2,
    float* __restrict__ out)
{
    const int lane = threadIdx.x & 31;
    const int w    = threadIdx.x >> 5;        // 0..8
    const int g    = w % 3;                   // dy group: dy = 3g..3g+2
    const int ri   = w / 3;                   // 0..2 within the r-tile
    const int b    = blockIdx.y;
    const int r    = blockIdx.x * 3 + ri - 4; // in2 row, -4..100
    const int x0   = lane * 4;

    const int   rc    = r < 0 ? 0 : (r > HH - 1 ? HH - 1 : r);
    const float rowok = (r >= 0 && r < HH) ? 1.0f : 0.0f;

    int  yv[3], yc[3];
    bool yok[3];
    #pragma unroll
    for (int t = 0; t < 3; t++) {
        const int y = r + 4 - (3 * g + t);
        yv[t]  = y;
        yok[t] = (y >= 0 && y < HH);
        yc[t]  = y < 0 ? 0 : (y > HH - 1 ? HH - 1 : y);
    }

    // clamped lane-edge window loads (garbage masked at epilogue)
    const int offL = (lane == 0)  ? 0 : -4;
    const int offR = (lane == 31) ? 0 :  4;

    ull acc[3][9][2];
    #pragma unroll
    for (int t = 0; t < 3; t++)
        #pragma unroll
        for (int d = 0; d < 9; d++) {
            acc[t][d][0] = 0ull;
            acc[t][d][1] = 0ull;
        }

    const float* p2 = in2 + ((size_t)b * CC) * HW + (size_t)rc * WW + x0;
    const float* p1a = in1 + ((size_t)b * CC) * HW + (size_t)yc[0] * WW + x0;
    const float* p1b = in1 + ((size_t)b * CC) * HW + (size_t)yc[1] * WW + x0;
    const float* p1c = in1 + ((size_t)b * CC) * HW + (size_t)yc[2] * WW + x0;

    #pragma unroll 2
    for (int c = 0; c < CC; c++) {
        // in2 window: w[k] = in2[rc, x0-4+k], k = 0..11 (pairs come in free)
        const ulonglong2 Lv = *(const ulonglong2*)(p2 + offL);
        const ulonglong2 Mv = *(const ulonglong2*)(p2);
        const ulonglong2 Rv = *(const ulonglong2*)(p2 + offR);
        const ulonglong2 A0 = *(const ulonglong2*)(p1a);
        const ulonglong2 A1 = *(const ulonglong2*)(p1b);
        const ulonglong2 A2 = *(const ulonglong2*)(p1c);
        p2  += HW;
        p1a += HW;
        p1b += HW;
        p1c += HW;

        // wp[k] = (w[k], w[k+1]); even k are natural register pairs
        ull wp[11];
        wp[0]  = Lv.x;  wp[2]  = Lv.y;  wp[4] = Mv.x;
        wp[6]  = Mv.y;  wp[8]  = Rv.x;  wp[10] = Rv.y;
        wp[1]  = pkmid(Lv.x, Lv.y);
        wp[3]  = pkmid(Lv.y, Mv.x);
        wp[5]  = pkmid(Mv.x, Mv.y);
        wp[7]  = pkmid(Mv.y, Rv.x);
        wp[9]  = pkmid(Rv.x, Rv.y);

        #pragma unroll
        for (int d = 0; d < 9; d++) {
            // pixels (x0,x0+1) use wp[d]; (x0+2,x0+3) use wp[d+2]
            fma2(acc[0][d][0], A0.x, wp[d]);
            fma2(acc[0][d][1], A0.y, wp[d + 2]);
            fma2(acc[1][d][0], A1.x, wp[d]);
            fma2(acc[1][d][1], A1.y, wp[d + 2]);
            fma2(acc[2][d][0], A2.x, wp[d]);
            fma2(acc[2][d][1], A2.y, wp[d + 2]);
        }
    }

    // epilogue: store to output rows y_t, masking padded contributions to 0
    #pragma unroll
    for (int t = 0; t < 3; t++) {
        if (!yok[t]) continue;                 // warp-uniform
        const int dy = 3 * g + t;
        #pragma unroll
        for (int d = 0; d < 9; d++) {
            const float2 lo = unpk(acc[t][d][0]);
            const float2 hi = unpk(acc[t][d][1]);
            float m[4];
            #pragma unroll
            for (int px = 0; px < 4; px++) {
                const int xs = x0 + px + d - 4;
                m[px] = (xs >= 0 && xs < WW) ? rowok : 0.0f;
            }
            float* po = out + (((((size_t)b * 9 + dy) * 9 + d) * HH + yv[t]) * WW) + x0;
            *(float4*)po = make_float4(lo.x * m[0], lo.y * m[1],
                                       hi.x * m[2], hi.y * m[3]);
        }
    }
}

extern "C" void kernel_launch(void* const* d_in, const int* in_sizes, int n_in,
                              void* d_out, int out_size)
{
    const float* in1 = (const float*)d_in[0];
    const float* in2 = (const float*)d_in[1];
    float* out = (float*)d_out;

    // blockIdx.x = r-tile (35 tiles cover r = -4..100), blockIdx.y = batch
    dim3 grid(35, 8, 1);
    corr_kernel<<<grid, 288>>>(in1, in2, out);
}

// round 4
// speedup vs baseline: 1.3594x; 1.0021x over previous
#include <cuda_runtime.h>

// Spatial correlation sampler: out[b][dy][dx][y][x] =
//   sum_c in1[b,c,y,x] * in2[b,c,y+dy-4,x+dx-4]   (zero padded), dy,dx in 0..8
//
// Round-4: same anti-diagonal decomposition as round 3 (thread = one in2 row r,
// one dy-group of 3, 4 x-pixels, 9 dx -> 27 f32x2-pair accumulators), but the
// channel loop batches TWO channels' loads (12 independent LDG.128) before any
// dependent pack/FMA work: MLP 6 -> 12, one scoreboard stall per 2 channels.

#define CC 128
#define HH 96
#define WW 128
#define HW (HH * WW)

typedef unsigned long long ull;

__device__ __forceinline__ void fma2(ull& acc, ull a, ull b) {
    asm("fma.rn.f32x2 %0, %1, %2, %0;" : "+l"(acc) : "l"(a), "l"(b));
}

// pair (lo = hi of a, hi = lo of b)
__device__ __forceinline__ ull pkmid(ull a, ull b) {
    ull r;
    asm("{ .reg .b32 al, ah, bl, bh;\n\t"
        "  mov.b64 {al, ah}, %1;\n\t"
        "  mov.b64 {bl, bh}, %2;\n\t"
        "  mov.b64 %0, {ah, bl}; }"
        : "=l"(r) : "l"(a), "l"(b));
    return r;
}

__device__ __forceinline__ float2 unpk(ull v) {
    unsigned lo, hi;
    asm("mov.b64 {%0,%1}, %2;" : "=r"(lo), "=r"(hi) : "l"(v));
    return make_float2(__uint_as_float(lo), __uint_as_float(hi));
}

__global__ __launch_bounds__(288, 1) void corr_kernel(
    const float* __restrict__ in1,
    const float* __restrict__ in2,
    float* __restrict__ out)
{
    const int lane = threadIdx.x & 31;
    const int w    = threadIdx.x >> 5;        // 0..8
    const int g    = w % 3;                   // dy group: dy = 3g..3g+2
    const int ri   = w / 3;                   // 0..2 within the r-tile
    const int b    = blockIdx.y;
    const int r    = blockIdx.x * 3 + ri - 4; // in2 row, -4..100
    const int x0   = lane * 4;

    const int   rc    = r < 0 ? 0 : (r > HH - 1 ? HH - 1 : r);
    const float rowok = (r >= 0 && r < HH) ? 1.0f : 0.0f;

    int  yv[3], yc[3];
    bool yok[3];
    #pragma unroll
    for (int t = 0; t < 3; t++) {
        const int y = r + 4 - (3 * g + t);
        yv[t]  = y;
        yok[t] = (y >= 0 && y < HH);
        yc[t]  = y < 0 ? 0 : (y > HH - 1 ? HH - 1 : y);
    }

    // clamped lane-edge window loads (garbage masked at epilogue)
    const int offL = (lane == 0)  ? 0 : -4;
    const int offR = (lane == 31) ? 0 :  4;

    ull acc[3][9][2];
    #pragma unroll
    for (int t = 0; t < 3; t++)
        #pragma unroll
        for (int d = 0; d < 9; d++) {
            acc[t][d][0] = 0ull;
            acc[t][d][1] = 0ull;
        }

    const float* p2  = in2 + ((size_t)b * CC) * HW + (size_t)rc   * WW + x0;
    const float* p1a = in1 + ((size_t)b * CC) * HW + (size_t)yc[0] * WW + x0;
    const float* p1b = in1 + ((size_t)b * CC) * HW + (size_t)yc[1] * WW + x0;
    const float* p1c = in1 + ((size_t)b * CC) * HW + (size_t)yc[2] * WW + x0;

    // -------- hot loop: 2 channels per trip, 12 batched LDG.128 --------
    #pragma unroll 1
    for (int c = 0; c < CC; c += 2) {
        ulonglong2 Lv[2], Mv[2], Rv[2], A0[2], A1[2], A2[2];

        // all 12 loads issued before any dependent math
        #pragma unroll
        for (int u = 0; u < 2; u++) {
            const size_t o = (size_t)u * HW;
            Lv[u] = *(const ulonglong2*)(p2  + o + offL);
            Mv[u] = *(const ulonglong2*)(p2  + o);
            Rv[u] = *(const ulonglong2*)(p2  + o + offR);
            A0[u] = *(const ulonglong2*)(p1a + o);
            A1[u] = *(const ulonglong2*)(p1b + o);
            A2[u] = *(const ulonglong2*)(p1c + o);
        }
        p2  += 2 * HW;
        p1a += 2 * HW;
        p1b += 2 * HW;
        p1c += 2 * HW;

        #pragma unroll
        for (int u = 0; u < 2; u++) {
            // wp[k] = (w[k], w[k+1]); even k are natural register pairs
            ull wp[11];
            wp[0]  = Lv[u].x;  wp[2]  = Lv[u].y;  wp[4]  = Mv[u].x;
            wp[6]  = Mv[u].y;  wp[8]  = Rv[u].x;  wp[10] = Rv[u].y;
            wp[1]  = pkmid(Lv[u].x, Lv[u].y);
            wp[3]  = pkmid(Lv[u].y, Mv[u].x);
            wp[5]  = pkmid(Mv[u].x, Mv[u].y);
            wp[7]  = pkmid(Mv[u].y, Rv[u].x);
            wp[9]  = pkmid(Rv[u].x, Rv[u].y);

            #pragma unroll
            for (int d = 0; d < 9; d++) {
                fma2(acc[0][d][0], A0[u].x, wp[d]);
                fma2(acc[0][d][1], A0[u].y, wp[d + 2]);
                fma2(acc[1][d][0], A1[u].x, wp[d]);
                fma2(acc[1][d][1], A1[u].y, wp[d + 2]);
                fma2(acc[2][d][0], A2[u].x, wp[d]);
                fma2(acc[2][d][1], A2[u].y, wp[d + 2]);
            }
        }
    }

    // -------- epilogue: mask padded contributions to exact zeros --------
    #pragma unroll
    for (int t = 0; t < 3; t++) {
        if (!yok[t]) continue;                 // warp-uniform
        const int dy = 3 * g + t;
        #pragma unroll
        for (int d = 0; d < 9; d++) {
            const float2 lo = unpk(acc[t][d][0]);
            const float2 hi = unpk(acc[t][d][1]);
            float m[4];
            #pragma unroll
            for (int px = 0; px < 4; px++) {
                const int xs = x0 + px + d - 4;
                m[px] = (xs >= 0 && xs < WW) ? rowok : 0.0f;
            }
            float* po = out + (((((size_t)b * 9 + dy) * 9 + d) * HH + yv[t]) * WW) + x0;
            *(float4*)po = make_float4(lo.x * m[0], lo.y * m[1],
                                       hi.x * m[2], hi.y * m[3]);
        }
    }
}

extern "C" void kernel_launch(void* const* d_in, const int* in_sizes, int n_in,
                              void* d_out, int out_size)
{
    const float* in1 = (const float*)d_in[0];
    const float* in2 = (const float*)d_in[1];
    float* out = (float*)d_out;

    // blockIdx.x = r-tile (35 tiles cover r = -4..100), blockIdx.y = batch
    dim3 grid(35, 8, 1);
    corr_kernel<<<grid, 288>>>(in1, in2, out);
}